// round 12
// baseline (speedup 1.0000x reference)
#include <cuda_runtime.h>
#include <cstdint>

#define NT 16     // NUM_TYPES
#define OD 128    // OUT_DIM
#define N_MAX 100000

typedef unsigned long long u64;

// Packed fp32x2 FMA (Blackwell FFMA2): d = a*b + c, two fp32 lanes per issue.
#define FMA2(d, a, b, c) \
    asm("fma.rn.f32x2 %0, %1, %2, %3;" : "=l"(d) : "l"(a), "l"(b), "l"(c))
#define PACK2(out, lo, hi) \
    asm("mov.b64 %0, {%1, %2};" : "=l"(out) : "f"(lo), "f"(hi))
#define UNPACK2(lo, hi, in) \
    asm("mov.b64 {%0, %1}, %2;" : "=f"(lo), "=f"(hi) : "l"(in))

// Scratch (allocation-free rule: __device__ globals). 16B-aligned for float4.
// g_p is stored PERMUTED within each 16-float row: position q*4+j holds
// logical element q+4j (q=0..3). Scatter lane q loads float4 #q =
// {p[q], p[q+4], p[q+8], p[q+12]} and REDs to natural msum positions q+4j;
// RED #j across the 4 lanes covers 16 CONTIGUOUS bytes (validated R8).
__device__ __align__(16) float g_p[N_MAX * NT];
__device__ __align__(16) float g_msum[N_MAX * NT];   // natural layout
__device__ int g_idx64;   // 1 if indices are int64, 0 if int32

// ---------------------------------------------------------------------------
// p = softmax(relu(r@W1+b1) @ Wp + bp)   ONE node per thread (max occupancy),
// FFMA2 packed. Prologue: zero msum + detect index width (fused k_init).
// Output stored in the q/4-permuted layout (see g_p comment).
// ---------------------------------------------------------------------------
__global__ void __launch_bounds__(256) k_compute_p(
        const float* __restrict__ r,
        const float* __restrict__ W1,
        const float* __restrict__ b1,
        const float* __restrict__ Wp,
        const float* __restrict__ bp,
        const void* __restrict__ src,
        int E, int n) {
    int gid = blockIdx.x * blockDim.x + threadIdx.x;
    int gtot = gridDim.x * blockDim.x;

    // --- fused init: detect index width + zero msum ---
    if (gid == 0) {
        const unsigned long long* p = (const unsigned long long*)src;
        int is64 = 1;
        int lim = (E / 2 < 16) ? E / 2 : 16;
        for (int k = 0; k < lim; k++) {
            if (p[k] > 0x7FFFFFFFULL) is64 = 0;
        }
        g_idx64 = is64;
    }
    for (int i = gid; i < n * 4; i += gtot)
        ((float4*)g_msum)[i] = make_float4(0.f, 0.f, 0.f, 0.f);

    // --- stage weights in shared ---
    __shared__ __align__(16) float sW1t[OD * NT];  // [j*16 + k] = W1[k*128 + j]
    __shared__ __align__(16) float sWp [OD * NT];  // [j*16 + t] = Wp[j*16 + t]
    __shared__ float sb1 [OD];
    __shared__ float sbp [NT];

    for (int i = threadIdx.x; i < OD * NT; i += blockDim.x) {
        int j = i >> 4, k = i & 15;
        sW1t[i] = W1[k * OD + j];
        sWp[i]  = Wp[i];
    }
    for (int i = threadIdx.x; i < OD; i += blockDim.x) sb1[i] = b1[i];
    if (threadIdx.x < NT) sbp[threadIdx.x] = bp[threadIdx.x];
    __syncthreads();

    int node = gid;
    if (node >= n) return;

    // r row pre-packed over k: rA2[i] = (r[2i], r[2i+1])
    u64 rA2[8];
    {
        const float4* rp = (const float4*)(r + (size_t)node * NT);
#pragma unroll
        for (int i = 0; i < 4; i++) {
            float4 v = rp[i];
            PACK2(rA2[i * 2 + 0], v.x, v.y);
            PACK2(rA2[i * 2 + 1], v.z, v.w);
        }
    }

    // accumulators packed over t: acc2[i] = (acc[2i], acc[2i+1]), init = bp
    u64 acc2[8];
#pragma unroll
    for (int i = 0; i < 8; i++) {
        PACK2(acc2[i], sbp[2 * i], sbp[2 * i + 1]);
    }

#pragma unroll 4
    for (int j = 0; j < OD; j++) {
        // W1t row j: 16 floats = 8 packed k-pairs (uniform broadcast LDS.128)
        const longlong2* w1p = (const longlong2*)(sW1t + j * NT);
        longlong2 wA = w1p[0], wB = w1p[1], wC = w1p[2], wD = w1p[3];

        u64 z2 = 0ULL;
        FMA2(z2, rA2[0], (u64)wA.x, z2);
        FMA2(z2, rA2[1], (u64)wA.y, z2);
        FMA2(z2, rA2[2], (u64)wB.x, z2);
        FMA2(z2, rA2[3], (u64)wB.y, z2);
        FMA2(z2, rA2[4], (u64)wC.x, z2);
        FMA2(z2, rA2[5], (u64)wC.y, z2);
        FMA2(z2, rA2[6], (u64)wD.x, z2);
        FMA2(z2, rA2[7], (u64)wD.y, z2);

        float zl, zh;
        UNPACK2(zl, zh, z2);
        float z = fmaxf((zl + zh) + sb1[j], 0.0f);
        u64 zz;
        PACK2(zz, z, z);

        // Wp row j: 16 floats = 8 packed t-pairs
        const longlong2* wpp = (const longlong2*)(sWp + j * NT);
        longlong2 pA = wpp[0], pB = wpp[1], pC = wpp[2], pD = wpp[3];

        FMA2(acc2[0], zz, (u64)pA.x, acc2[0]);
        FMA2(acc2[1], zz, (u64)pA.y, acc2[1]);
        FMA2(acc2[2], zz, (u64)pB.x, acc2[2]);
        FMA2(acc2[3], zz, (u64)pB.y, acc2[3]);
        FMA2(acc2[4], zz, (u64)pC.x, acc2[4]);
        FMA2(acc2[5], zz, (u64)pC.y, acc2[5]);
        FMA2(acc2[6], zz, (u64)pD.x, acc2[6]);
        FMA2(acc2[7], zz, (u64)pD.y, acc2[7]);
    }

    float acc[NT];
#pragma unroll
    for (int i = 0; i < 8; i++) {
        UNPACK2(acc[2 * i], acc[2 * i + 1], acc2[i]);
    }

    float m = acc[0];
#pragma unroll
    for (int t = 1; t < NT; t++) m = fmaxf(m, acc[t]);
    float s = 0.0f;
#pragma unroll
    for (int t = 0; t < NT; t++) { acc[t] = __expf(acc[t] - m); s += acc[t]; }
    float inv = 1.0f / s;
    float4* o = (float4*)(g_p + (size_t)node * NT);
    // PERMUTED store: float4 #q = {p[q], p[q+4], p[q+8], p[q+12]}
    o[0] = make_float4(acc[0]*inv, acc[4]*inv, acc[8]*inv,  acc[12]*inv);
    o[1] = make_float4(acc[1]*inv, acc[5]*inv, acc[9]*inv,  acc[13]*inv);
    o[2] = make_float4(acc[2]*inv, acc[6]*inv, acc[10]*inv, acc[14]*inv);
    o[3] = make_float4(acc[3]*inv, acc[7]*inv, acc[11]*inv, acc[15]*inv);
}

// ---------------------------------------------------------------------------
// Scatter: msum[dst] += p[src].  4 lanes per edge, FOUR edges per thread:
// two longlong2 (or one int4) loads per index array. RED #j across an edge's
// 4 lanes covers 16 contiguous bytes. No degree atomics (row-sum trick).
// ---------------------------------------------------------------------------
__global__ void k_scatter(const void* __restrict__ srcv,
                          const void* __restrict__ dstv,
                          int E, int n) {
    int gid = blockIdx.x * blockDim.x + threadIdx.x;
    int quad = gid >> 2;
    int e0 = quad * 4;
    if (e0 >= E) return;
    int q = gid & 3;

    int s[4], d[4];
    int cnt;
    if (e0 + 3 < E) {
        cnt = 4;
        if (g_idx64) {
            const longlong2* ps = (const longlong2*)srcv + quad * 2;
            const longlong2* pd = (const longlong2*)dstv + quad * 2;
            longlong2 sa = ps[0], sb = ps[1];
            longlong2 da = pd[0], db = pd[1];
            s[0] = (int)sa.x; s[1] = (int)sa.y; s[2] = (int)sb.x; s[3] = (int)sb.y;
            d[0] = (int)da.x; d[1] = (int)da.y; d[2] = (int)db.x; d[3] = (int)db.y;
        } else {
            int4 sv = ((const int4*)srcv)[quad];
            int4 dv = ((const int4*)dstv)[quad];
            s[0] = sv.x; s[1] = sv.y; s[2] = sv.z; s[3] = sv.w;
            d[0] = dv.x; d[1] = dv.y; d[2] = dv.z; d[3] = dv.w;
        }
    } else {
        cnt = E - e0;
        for (int i = 0; i < cnt; i++) {
            s[i] = g_idx64 ? (int)((const long long*)srcv)[e0 + i]
                           : ((const int*)srcv)[e0 + i];
            d[i] = g_idx64 ? (int)((const long long*)dstv)[e0 + i]
                           : ((const int*)dstv)[e0 + i];
        }
        for (int i = cnt; i < 4; i++) { s[i] = 0; d[i] = 0; }
    }

#pragma unroll
    for (int i = 0; i < 4; i++) {
        if (i >= cnt) break;
        int ss = min(max(s[i], 0), n - 1);
        int dd = min(max(d[i], 0), n - 1);
        const float4 v = __ldg((const float4*)(g_p + (size_t)ss * NT + q * 4));
        float* row = g_msum + (size_t)dd * NT + q;
        atomicAdd(row + 0,  v.x);
        atomicAdd(row + 4,  v.y);
        atomicAdd(row + 8,  v.z);
        atomicAdd(row + 12, v.w);
    }
}

// ---------------------------------------------------------------------------
// Normalize: msum[node] *= 1/max(round(rowsum),1).  4 threads per node,
// rowsum via 2 butterfly shuffles (p rows sum to 1 -> rowsum == degree).
// ---------------------------------------------------------------------------
__global__ void k_norm(int n) {
    int gid = blockIdx.x * blockDim.x + threadIdx.x;
    int node = gid >> 2;
    if (node >= n) return;

    float4* p = (float4*)g_msum + (size_t)gid;
    float4 v = *p;
    float s = (v.x + v.y) + (v.z + v.w);
    s += __shfl_xor_sync(0xffffffffu, s, 1);
    s += __shfl_xor_sync(0xffffffffu, s, 2);
    float invd = 1.0f / fmaxf(nearbyintf(s), 1.0f);
    v.x *= invd; v.y *= invd; v.z *= invd; v.w *= invd;
    *p = v;
}

// ---------------------------------------------------------------------------
// out = relu(n_dist @ Wf + bf)   (n_dist = pre-normalized msum)
// j = tid&127 is loop-invariant: the 16 weights live in REGISTERS.
// ---------------------------------------------------------------------------
__global__ void __launch_bounds__(256) k_final(
        const float* __restrict__ Wf,
        const float* __restrict__ bf,
        float* __restrict__ out,
        int n) {
    int j = threadIdx.x & 127;
    float w[NT];
#pragma unroll
    for (int t = 0; t < NT; t++) w[t] = Wf[t * OD + j];
    float bj = bf[j];

    int total  = n * OD;
    int stride = gridDim.x * blockDim.x;
    for (int gid = blockIdx.x * blockDim.x + threadIdx.x; gid < total; gid += stride) {
        int node = gid >> 7;

        const float4* ms = (const float4*)(g_msum + (size_t)node * NT);
        float4 m0 = ms[0], m1 = ms[1], m2 = ms[2], m3 = ms[3];

        float acc = bj;
        acc = fmaf(m0.x, w[0],  acc); acc = fmaf(m0.y, w[1],  acc);
        acc = fmaf(m0.z, w[2],  acc); acc = fmaf(m0.w, w[3],  acc);
        acc = fmaf(m1.x, w[4],  acc); acc = fmaf(m1.y, w[5],  acc);
        acc = fmaf(m1.z, w[6],  acc); acc = fmaf(m1.w, w[7],  acc);
        acc = fmaf(m2.x, w[8],  acc); acc = fmaf(m2.y, w[9],  acc);
        acc = fmaf(m2.z, w[10], acc); acc = fmaf(m2.w, w[11], acc);
        acc = fmaf(m3.x, w[12], acc); acc = fmaf(m3.y, w[13], acc);
        acc = fmaf(m3.z, w[14], acc); acc = fmaf(m3.w, w[15], acc);

        out[gid] = fmaxf(acc, 0.0f);
    }
}

// ---------------------------------------------------------------------------
// Inputs (metadata order): r, src, dst, W1, b1, Wp, bp, Wf, bf
// ---------------------------------------------------------------------------
extern "C" void kernel_launch(void* const* d_in, const int* in_sizes, int n_in,
                              void* d_out, int out_size) {
    const float* r   = (const float*)d_in[0];
    const void*  src = d_in[1];
    const void*  dst = d_in[2];
    const float* W1  = (const float*)d_in[3];
    const float* b1  = (const float*)d_in[4];
    const float* Wp  = (const float*)d_in[5];
    const float* bp  = (const float*)d_in[6];
    const float* Wf  = (const float*)d_in[7];
    const float* bf  = (const float*)d_in[8];
    float*       out = (float*)d_out;

    int n = in_sizes[0] / NT;
    int E = in_sizes[1];
    if (n > N_MAX) n = N_MAX;

    k_compute_p<<<(n + 255) / 256, 256>>>(r, W1, b1, Wp, bp, src, E, n);
    {
        long long threads = (long long)((E + 3) / 4) * 4;
        int blocks = (int)((threads + 255) / 256);
        k_scatter<<<blocks, 256>>>(src, dst, E, n);
    }
    k_norm<<<(n * 4 + 255) / 256, 256>>>(n);
    k_final<<<3200, 256>>>(Wf, bf, out, n);
}

// round 13
// speedup vs baseline: 1.0879x; 1.0879x over previous
#include <cuda_runtime.h>
#include <cstdint>

#define NT 16     // NUM_TYPES
#define OD 128    // OUT_DIM
#define N_MAX 100000

typedef unsigned long long u64;

// Packed fp32x2 FMA (Blackwell FFMA2): d = a*b + c, two fp32 lanes per issue.
#define FMA2(d, a, b, c) \
    asm("fma.rn.f32x2 %0, %1, %2, %3;" : "=l"(d) : "l"(a), "l"(b), "l"(c))
#define PACK2(out, lo, hi) \
    asm("mov.b64 %0, {%1, %2};" : "=l"(out) : "f"(lo), "f"(hi))
#define UNPACK2(lo, hi, in) \
    asm("mov.b64 {%0, %1}, %2;" : "=f"(lo), "=f"(hi) : "l"(in))

// Scratch (allocation-free rule: __device__ globals). 16B-aligned for float4.
// g_p is stored PERMUTED within each 16-float row: position q*4+j holds
// logical element q+4j (q=0..3). Scatter lane q loads float4 #q =
// {p[q], p[q+4], p[q+8], p[q+12]} and REDs to natural msum positions q+4j;
// RED #j across the 4 lanes covers 16 CONTIGUOUS bytes (validated R8).
__device__ __align__(16) float g_p[N_MAX * NT];
__device__ __align__(16) float g_msum[N_MAX * NT];   // natural layout
__device__ int g_idx64;   // 1 if indices are int64, 0 if int32

// ---------------------------------------------------------------------------
// p = softmax(relu(r@W1+b1) @ Wp + bp)   TWO nodes per thread (ILP-2 FFMA2
// chains — validated R11). Prologue fuses init: zero msum + detect idx width.
// Output stored in the q/4-permuted layout (see g_p comment).
// ---------------------------------------------------------------------------
__global__ void __launch_bounds__(128) k_compute_p(
        const float* __restrict__ r,
        const float* __restrict__ W1,
        const float* __restrict__ b1,
        const float* __restrict__ Wp,
        const float* __restrict__ bp,
        const void* __restrict__ src,
        int E, int n) {
    int gid = blockIdx.x * blockDim.x + threadIdx.x;
    int gtot = gridDim.x * blockDim.x;

    // --- fused init ---
    if (gid == 0) {
        const unsigned long long* p = (const unsigned long long*)src;
        int is64 = 1;
        int lim = (E / 2 < 16) ? E / 2 : 16;
        for (int k = 0; k < lim; k++) {
            if (p[k] > 0x7FFFFFFFULL) is64 = 0;
        }
        g_idx64 = is64;
    }
    for (int i = gid; i < n * 4; i += gtot)
        ((float4*)g_msum)[i] = make_float4(0.f, 0.f, 0.f, 0.f);

    __shared__ __align__(16) float sW1t[OD * NT];  // [j*16 + k] = W1[k*128 + j]
    __shared__ __align__(16) float sWp [OD * NT];  // [j*16 + t] = Wp[j*16 + t]
    __shared__ float sb1 [OD];
    __shared__ float sbp [NT];

    for (int i = threadIdx.x; i < OD * NT; i += blockDim.x) {
        int j = i >> 4, k = i & 15;
        sW1t[i] = W1[k * OD + j];
        sWp[i]  = Wp[i];
    }
    for (int i = threadIdx.x; i < OD; i += blockDim.x) sb1[i] = b1[i];
    if (threadIdx.x < NT) sbp[threadIdx.x] = bp[threadIdx.x];
    __syncthreads();

    int node0 = gid * 2;
    if (node0 >= n) return;
    bool two = (node0 + 1 < n);

    // r rows pre-packed over k
    u64 rA2[8], rB2[8];
    {
        const float4* rp0 = (const float4*)(r + (size_t)node0 * NT);
#pragma unroll
        for (int i = 0; i < 4; i++) {
            float4 v = rp0[i];
            PACK2(rA2[i * 2 + 0], v.x, v.y);
            PACK2(rA2[i * 2 + 1], v.z, v.w);
        }
        if (two) {
            const float4* rp1 = (const float4*)(r + (size_t)(node0 + 1) * NT);
#pragma unroll
            for (int i = 0; i < 4; i++) {
                float4 v = rp1[i];
                PACK2(rB2[i * 2 + 0], v.x, v.y);
                PACK2(rB2[i * 2 + 1], v.z, v.w);
            }
        } else {
#pragma unroll
            for (int i = 0; i < 8; i++) rB2[i] = 0ULL;
        }
    }

    u64 accA2[8], accB2[8];
#pragma unroll
    for (int i = 0; i < 8; i++) {
        u64 b2; PACK2(b2, sbp[2 * i], sbp[2 * i + 1]);
        accA2[i] = b2; accB2[i] = b2;
    }

#pragma unroll 2
    for (int j = 0; j < OD; j++) {
        const longlong2* w1p = (const longlong2*)(sW1t + j * NT);
        longlong2 wA = w1p[0], wB = w1p[1], wC = w1p[2], wD = w1p[3];

        u64 zA2 = 0ULL, zB2 = 0ULL;
        FMA2(zA2, rA2[0], (u64)wA.x, zA2); FMA2(zB2, rB2[0], (u64)wA.x, zB2);
        FMA2(zA2, rA2[1], (u64)wA.y, zA2); FMA2(zB2, rB2[1], (u64)wA.y, zB2);
        FMA2(zA2, rA2[2], (u64)wB.x, zA2); FMA2(zB2, rB2[2], (u64)wB.x, zB2);
        FMA2(zA2, rA2[3], (u64)wB.y, zA2); FMA2(zB2, rB2[3], (u64)wB.y, zB2);
        FMA2(zA2, rA2[4], (u64)wC.x, zA2); FMA2(zB2, rB2[4], (u64)wC.x, zB2);
        FMA2(zA2, rA2[5], (u64)wC.y, zA2); FMA2(zB2, rB2[5], (u64)wC.y, zB2);
        FMA2(zA2, rA2[6], (u64)wD.x, zA2); FMA2(zB2, rB2[6], (u64)wD.x, zB2);
        FMA2(zA2, rA2[7], (u64)wD.y, zA2); FMA2(zB2, rB2[7], (u64)wD.y, zB2);

        float bj = sb1[j];
        float zAl, zAh, zBl, zBh;
        UNPACK2(zAl, zAh, zA2);
        UNPACK2(zBl, zBh, zB2);
        float zA = fmaxf((zAl + zAh) + bj, 0.0f);
        float zB = fmaxf((zBl + zBh) + bj, 0.0f);
        u64 zzA, zzB;
        PACK2(zzA, zA, zA);
        PACK2(zzB, zB, zB);

        const longlong2* wpp = (const longlong2*)(sWp + j * NT);
        longlong2 pA = wpp[0], pB = wpp[1], pC = wpp[2], pD = wpp[3];

        FMA2(accA2[0], zzA, (u64)pA.x, accA2[0]); FMA2(accB2[0], zzB, (u64)pA.x, accB2[0]);
        FMA2(accA2[1], zzA, (u64)pA.y, accA2[1]); FMA2(accB2[1], zzB, (u64)pA.y, accB2[1]);
        FMA2(accA2[2], zzA, (u64)pB.x, accA2[2]); FMA2(accB2[2], zzB, (u64)pB.x, accB2[2]);
        FMA2(accA2[3], zzA, (u64)pB.y, accA2[3]); FMA2(accB2[3], zzB, (u64)pB.y, accB2[3]);
        FMA2(accA2[4], zzA, (u64)pC.x, accA2[4]); FMA2(accB2[4], zzB, (u64)pC.x, accB2[4]);
        FMA2(accA2[5], zzA, (u64)pC.y, accA2[5]); FMA2(accB2[5], zzB, (u64)pC.y, accB2[5]);
        FMA2(accA2[6], zzA, (u64)pD.x, accA2[6]); FMA2(accB2[6], zzB, (u64)pD.x, accB2[6]);
        FMA2(accA2[7], zzA, (u64)pD.y, accA2[7]); FMA2(accB2[7], zzB, (u64)pD.y, accB2[7]);
    }

    float accA[NT], accB[NT];
#pragma unroll
    for (int i = 0; i < 8; i++) {
        UNPACK2(accA[2 * i], accA[2 * i + 1], accA2[i]);
        UNPACK2(accB[2 * i], accB[2 * i + 1], accB2[i]);
    }

    {
        float m = accA[0];
#pragma unroll
        for (int t = 1; t < NT; t++) m = fmaxf(m, accA[t]);
        float s = 0.0f;
#pragma unroll
        for (int t = 0; t < NT; t++) { accA[t] = __expf(accA[t] - m); s += accA[t]; }
        float inv = 1.0f / s;
        float4* o = (float4*)(g_p + (size_t)node0 * NT);
        o[0] = make_float4(accA[0]*inv, accA[4]*inv, accA[8]*inv,  accA[12]*inv);
        o[1] = make_float4(accA[1]*inv, accA[5]*inv, accA[9]*inv,  accA[13]*inv);
        o[2] = make_float4(accA[2]*inv, accA[6]*inv, accA[10]*inv, accA[14]*inv);
        o[3] = make_float4(accA[3]*inv, accA[7]*inv, accA[11]*inv, accA[15]*inv);
    }
    if (two) {
        float m = accB[0];
#pragma unroll
        for (int t = 1; t < NT; t++) m = fmaxf(m, accB[t]);
        float s = 0.0f;
#pragma unroll
        for (int t = 0; t < NT; t++) { accB[t] = __expf(accB[t] - m); s += accB[t]; }
        float inv = 1.0f / s;
        float4* o = (float4*)(g_p + (size_t)(node0 + 1) * NT);
        o[0] = make_float4(accB[0]*inv, accB[4]*inv, accB[8]*inv,  accB[12]*inv);
        o[1] = make_float4(accB[1]*inv, accB[5]*inv, accB[9]*inv,  accB[13]*inv);
        o[2] = make_float4(accB[2]*inv, accB[6]*inv, accB[10]*inv, accB[14]*inv);
        o[3] = make_float4(accB[3]*inv, accB[7]*inv, accB[11]*inv, accB[15]*inv);
    }
}

// ---------------------------------------------------------------------------
// Scatter: msum[dst] += p[src].  4 lanes per edge, 2 edges per thread
// (validated R10, 141.4us total). RED #j across an edge's 4 lanes covers
// 16 contiguous bytes. No degree atomics (row-sum trick).
// ---------------------------------------------------------------------------
__global__ void k_scatter(const void* __restrict__ srcv,
                          const void* __restrict__ dstv,
                          int E, int n) {
    int gid = blockIdx.x * blockDim.x + threadIdx.x;
    int pair = gid >> 2;
    int e0 = pair * 2;
    if (e0 >= E) return;
    int q = gid & 3;
    bool has2 = (e0 + 1 < E);

    int s0, d0, s1 = 0, d1 = 0;
    if (g_idx64) {
        const longlong2* ps = (const longlong2*)srcv;
        const longlong2* pd = (const longlong2*)dstv;
        longlong2 sv = ps[pair];
        longlong2 dv = pd[pair];
        s0 = (int)sv.x; s1 = (int)sv.y;
        d0 = (int)dv.x; d1 = (int)dv.y;
    } else {
        const int2* ps = (const int2*)srcv;
        const int2* pd = (const int2*)dstv;
        int2 sv = ps[pair];
        int2 dv = pd[pair];
        s0 = sv.x; s1 = sv.y;
        d0 = dv.x; d1 = dv.y;
    }
    s0 = min(max(s0, 0), n - 1);
    d0 = min(max(d0, 0), n - 1);

    const float4 v0 = __ldg((const float4*)(g_p + (size_t)s0 * NT + q * 4));
    float* row0 = g_msum + (size_t)d0 * NT + q;
    atomicAdd(row0 + 0,  v0.x);
    atomicAdd(row0 + 4,  v0.y);
    atomicAdd(row0 + 8,  v0.z);
    atomicAdd(row0 + 12, v0.w);

    if (has2) {
        s1 = min(max(s1, 0), n - 1);
        d1 = min(max(d1, 0), n - 1);
        const float4 v1 = __ldg((const float4*)(g_p + (size_t)s1 * NT + q * 4));
        float* row1 = g_msum + (size_t)d1 * NT + q;
        atomicAdd(row1 + 0,  v1.x);
        atomicAdd(row1 + 4,  v1.y);
        atomicAdd(row1 + 8,  v1.z);
        atomicAdd(row1 + 12, v1.w);
    }
}

// ---------------------------------------------------------------------------
// Normalize: msum[node] *= 1/max(round(rowsum),1).  4 threads per node.
// ---------------------------------------------------------------------------
__global__ void k_norm(int n) {
    int gid = blockIdx.x * blockDim.x + threadIdx.x;
    int node = gid >> 2;
    if (node >= n) return;

    float4* p = (float4*)g_msum + (size_t)gid;
    float4 v = *p;
    float s = (v.x + v.y) + (v.z + v.w);
    s += __shfl_xor_sync(0xffffffffu, s, 1);
    s += __shfl_xor_sync(0xffffffffu, s, 2);
    float invd = 1.0f / fmaxf(nearbyintf(s), 1.0f);
    v.x *= invd; v.y *= invd; v.z *= invd; v.w *= invd;
    *p = v;
}

// ---------------------------------------------------------------------------
// out = relu(n_dist @ Wf + bf)   (n_dist = pre-normalized msum)
// v2: weights packed as 8 u64 t-pairs; msum loaded as longlong2 (direct
// packed operands); TWO outputs (different nodes) per loop iteration ->
// 8 LDG.128 in flight + two independent FFMA2 chains.
// j = tid&127 is loop-invariant (stride multiple of 128).
// ---------------------------------------------------------------------------
__global__ void __launch_bounds__(256) k_final(
        const float* __restrict__ Wf,
        const float* __restrict__ bf,
        float* __restrict__ out,
        int n) {
    int j = threadIdx.x & 127;
    u64 w2[8];
#pragma unroll
    for (int i = 0; i < 8; i++) {
        PACK2(w2[i], Wf[(2 * i) * OD + j], Wf[(2 * i + 1) * OD + j]);
    }
    float bj = bf[j];

    int total  = n * OD;
    int stride = gridDim.x * blockDim.x;   // multiple of 128
    int gid = blockIdx.x * blockDim.x + threadIdx.x;

    for (int e0 = gid; e0 < total; e0 += 2 * stride) {
        int e1 = e0 + stride;
        bool has1 = (e1 < total);

        const longlong2* msA = (const longlong2*)(g_msum + (size_t)(e0 >> 7) * NT);
        longlong2 a0 = msA[0], a1 = msA[1], a2 = msA[2], a3 = msA[3];
        longlong2 b0, b1, b2, b3;
        if (has1) {
            const longlong2* msB = (const longlong2*)(g_msum + (size_t)(e1 >> 7) * NT);
            b0 = msB[0]; b1 = msB[1]; b2 = msB[2]; b3 = msB[3];
        }

        u64 accA = 0ULL, accB = 0ULL;
        FMA2(accA, (u64)a0.x, w2[0], accA);
        FMA2(accA, (u64)a0.y, w2[1], accA);
        FMA2(accA, (u64)a1.x, w2[2], accA);
        FMA2(accA, (u64)a1.y, w2[3], accA);
        FMA2(accA, (u64)a2.x, w2[4], accA);
        FMA2(accA, (u64)a2.y, w2[5], accA);
        FMA2(accA, (u64)a3.x, w2[6], accA);
        FMA2(accA, (u64)a3.y, w2[7], accA);
        float al, ah;
        UNPACK2(al, ah, accA);
        out[e0] = fmaxf((al + ah) + bj, 0.0f);

        if (has1) {
            FMA2(accB, (u64)b0.x, w2[0], accB);
            FMA2(accB, (u64)b0.y, w2[1], accB);
            FMA2(accB, (u64)b1.x, w2[2], accB);
            FMA2(accB, (u64)b1.y, w2[3], accB);
            FMA2(accB, (u64)b2.x, w2[4], accB);
            FMA2(accB, (u64)b2.y, w2[5], accB);
            FMA2(accB, (u64)b3.x, w2[6], accB);
            FMA2(accB, (u64)b3.y, w2[7], accB);
            float bl, bh;
            UNPACK2(bl, bh, accB);
            out[e1] = fmaxf((bl + bh) + bj, 0.0f);
        }
    }
}

// ---------------------------------------------------------------------------
// Inputs (metadata order): r, src, dst, W1, b1, Wp, bp, Wf, bf
// ---------------------------------------------------------------------------
extern "C" void kernel_launch(void* const* d_in, const int* in_sizes, int n_in,
                              void* d_out, int out_size) {
    const float* r   = (const float*)d_in[0];
    const void*  src = d_in[1];
    const void*  dst = d_in[2];
    const float* W1  = (const float*)d_in[3];
    const float* b1  = (const float*)d_in[4];
    const float* Wp  = (const float*)d_in[5];
    const float* bp  = (const float*)d_in[6];
    const float* Wf  = (const float*)d_in[7];
    const float* bf  = (const float*)d_in[8];
    float*       out = (float*)d_out;

    int n = in_sizes[0] / NT;
    int E = in_sizes[1];
    if (n > N_MAX) n = N_MAX;

    k_compute_p<<<((n + 1) / 2 + 127) / 128, 128>>>(r, W1, b1, Wp, bp, src, E, n);
    {
        long long threads = (long long)((E + 1) / 2) * 4;
        int blocks = (int)((threads + 255) / 256);
        k_scatter<<<blocks, 256>>>(src, dst, E, n);
    }
    k_norm<<<(n * 4 + 255) / 256, 256>>>(n);
    k_final<<<3200, 256>>>(Wf, bf, out, n);
}

// round 14
// speedup vs baseline: 1.1979x; 1.1011x over previous
#include <cuda_runtime.h>
#include <cstdint>

#define NT 16     // NUM_TYPES
#define OD 128    // OUT_DIM
#define N_MAX 100000
#define TILE_N 64 // nodes staged per block iteration in k_final

typedef unsigned long long u64;

// Packed fp32x2 FMA (Blackwell FFMA2): d = a*b + c, two fp32 lanes per issue.
#define FMA2(d, a, b, c) \
    asm("fma.rn.f32x2 %0, %1, %2, %3;" : "=l"(d) : "l"(a), "l"(b), "l"(c))
#define PACK2(out, lo, hi) \
    asm("mov.b64 %0, {%1, %2};" : "=l"(out) : "f"(lo), "f"(hi))
#define UNPACK2(lo, hi, in) \
    asm("mov.b64 {%0, %1}, %2;" : "=f"(lo), "=f"(hi) : "l"(in))

// Scratch (allocation-free rule: __device__ globals). 16B-aligned for float4.
// g_p is stored PERMUTED within each 16-float row: position q*4+j holds
// logical element q+4j (q=0..3). Scatter lane q loads float4 #q =
// {p[q], p[q+4], p[q+8], p[q+12]} and REDs to natural msum positions q+4j;
// RED #j across the 4 lanes covers 16 CONTIGUOUS bytes (validated R8).
__device__ __align__(16) float g_p[N_MAX * NT];
__device__ __align__(16) float g_msum[N_MAX * NT];   // natural layout
__device__ int g_idx64;   // 1 if indices are int64, 0 if int32

// ---------------------------------------------------------------------------
// p = softmax(relu(r@W1+b1) @ Wp + bp)   TWO nodes per thread (ILP-2 FFMA2
// chains — validated R11/R13). Prologue fuses init: zero msum + detect width.
// Output stored in the q/4-permuted layout (see g_p comment).
// ---------------------------------------------------------------------------
__global__ void __launch_bounds__(128) k_compute_p(
        const float* __restrict__ r,
        const float* __restrict__ W1,
        const float* __restrict__ b1,
        const float* __restrict__ Wp,
        const float* __restrict__ bp,
        const void* __restrict__ src,
        int E, int n) {
    int gid = blockIdx.x * blockDim.x + threadIdx.x;
    int gtot = gridDim.x * blockDim.x;

    // --- fused init ---
    if (gid == 0) {
        const unsigned long long* p = (const unsigned long long*)src;
        int is64 = 1;
        int lim = (E / 2 < 16) ? E / 2 : 16;
        for (int k = 0; k < lim; k++) {
            if (p[k] > 0x7FFFFFFFULL) is64 = 0;
        }
        g_idx64 = is64;
    }
    for (int i = gid; i < n * 4; i += gtot)
        ((float4*)g_msum)[i] = make_float4(0.f, 0.f, 0.f, 0.f);

    __shared__ __align__(16) float sW1t[OD * NT];  // [j*16 + k] = W1[k*128 + j]
    __shared__ __align__(16) float sWp [OD * NT];  // [j*16 + t] = Wp[j*16 + t]
    __shared__ float sb1 [OD];
    __shared__ float sbp [NT];

    for (int i = threadIdx.x; i < OD * NT; i += blockDim.x) {
        int j = i >> 4, k = i & 15;
        sW1t[i] = W1[k * OD + j];
        sWp[i]  = Wp[i];
    }
    for (int i = threadIdx.x; i < OD; i += blockDim.x) sb1[i] = b1[i];
    if (threadIdx.x < NT) sbp[threadIdx.x] = bp[threadIdx.x];
    __syncthreads();

    int node0 = gid * 2;
    if (node0 >= n) return;
    bool two = (node0 + 1 < n);

    u64 rA2[8], rB2[8];
    {
        const float4* rp0 = (const float4*)(r + (size_t)node0 * NT);
#pragma unroll
        for (int i = 0; i < 4; i++) {
            float4 v = rp0[i];
            PACK2(rA2[i * 2 + 0], v.x, v.y);
            PACK2(rA2[i * 2 + 1], v.z, v.w);
        }
        if (two) {
            const float4* rp1 = (const float4*)(r + (size_t)(node0 + 1) * NT);
#pragma unroll
            for (int i = 0; i < 4; i++) {
                float4 v = rp1[i];
                PACK2(rB2[i * 2 + 0], v.x, v.y);
                PACK2(rB2[i * 2 + 1], v.z, v.w);
            }
        } else {
#pragma unroll
            for (int i = 0; i < 8; i++) rB2[i] = 0ULL;
        }
    }

    u64 accA2[8], accB2[8];
#pragma unroll
    for (int i = 0; i < 8; i++) {
        u64 b2; PACK2(b2, sbp[2 * i], sbp[2 * i + 1]);
        accA2[i] = b2; accB2[i] = b2;
    }

#pragma unroll 2
    for (int j = 0; j < OD; j++) {
        const longlong2* w1p = (const longlong2*)(sW1t + j * NT);
        longlong2 wA = w1p[0], wB = w1p[1], wC = w1p[2], wD = w1p[3];

        u64 zA2 = 0ULL, zB2 = 0ULL;
        FMA2(zA2, rA2[0], (u64)wA.x, zA2); FMA2(zB2, rB2[0], (u64)wA.x, zB2);
        FMA2(zA2, rA2[1], (u64)wA.y, zA2); FMA2(zB2, rB2[1], (u64)wA.y, zB2);
        FMA2(zA2, rA2[2], (u64)wB.x, zA2); FMA2(zB2, rB2[2], (u64)wB.x, zB2);
        FMA2(zA2, rA2[3], (u64)wB.y, zA2); FMA2(zB2, rB2[3], (u64)wB.y, zB2);
        FMA2(zA2, rA2[4], (u64)wC.x, zA2); FMA2(zB2, rB2[4], (u64)wC.x, zB2);
        FMA2(zA2, rA2[5], (u64)wC.y, zA2); FMA2(zB2, rB2[5], (u64)wC.y, zB2);
        FMA2(zA2, rA2[6], (u64)wD.x, zA2); FMA2(zB2, rB2[6], (u64)wD.x, zB2);
        FMA2(zA2, rA2[7], (u64)wD.y, zA2); FMA2(zB2, rB2[7], (u64)wD.y, zB2);

        float bj = sb1[j];
        float zAl, zAh, zBl, zBh;
        UNPACK2(zAl, zAh, zA2);
        UNPACK2(zBl, zBh, zB2);
        float zA = fmaxf((zAl + zAh) + bj, 0.0f);
        float zB = fmaxf((zBl + zBh) + bj, 0.0f);
        u64 zzA, zzB;
        PACK2(zzA, zA, zA);
        PACK2(zzB, zB, zB);

        const longlong2* wpp = (const longlong2*)(sWp + j * NT);
        longlong2 pA = wpp[0], pB = wpp[1], pC = wpp[2], pD = wpp[3];

        FMA2(accA2[0], zzA, (u64)pA.x, accA2[0]); FMA2(accB2[0], zzB, (u64)pA.x, accB2[0]);
        FMA2(accA2[1], zzA, (u64)pA.y, accA2[1]); FMA2(accB2[1], zzB, (u64)pA.y, accB2[1]);
        FMA2(accA2[2], zzA, (u64)pB.x, accA2[2]); FMA2(accB2[2], zzB, (u64)pB.x, accB2[2]);
        FMA2(accA2[3], zzA, (u64)pB.y, accA2[3]); FMA2(accB2[3], zzB, (u64)pB.y, accB2[3]);
        FMA2(accA2[4], zzA, (u64)pC.x, accA2[4]); FMA2(accB2[4], zzB, (u64)pC.x, accB2[4]);
        FMA2(accA2[5], zzA, (u64)pC.y, accA2[5]); FMA2(accB2[5], zzB, (u64)pC.y, accB2[5]);
        FMA2(accA2[6], zzA, (u64)pD.x, accA2[6]); FMA2(accB2[6], zzB, (u64)pD.x, accB2[6]);
        FMA2(accA2[7], zzA, (u64)pD.y, accA2[7]); FMA2(accB2[7], zzB, (u64)pD.y, accB2[7]);
    }

    float accA[NT], accB[NT];
#pragma unroll
    for (int i = 0; i < 8; i++) {
        UNPACK2(accA[2 * i], accA[2 * i + 1], accA2[i]);
        UNPACK2(accB[2 * i], accB[2 * i + 1], accB2[i]);
    }

    {
        float m = accA[0];
#pragma unroll
        for (int t = 1; t < NT; t++) m = fmaxf(m, accA[t]);
        float s = 0.0f;
#pragma unroll
        for (int t = 0; t < NT; t++) { accA[t] = __expf(accA[t] - m); s += accA[t]; }
        float inv = 1.0f / s;
        float4* o = (float4*)(g_p + (size_t)node0 * NT);
        o[0] = make_float4(accA[0]*inv, accA[4]*inv, accA[8]*inv,  accA[12]*inv);
        o[1] = make_float4(accA[1]*inv, accA[5]*inv, accA[9]*inv,  accA[13]*inv);
        o[2] = make_float4(accA[2]*inv, accA[6]*inv, accA[10]*inv, accA[14]*inv);
        o[3] = make_float4(accA[3]*inv, accA[7]*inv, accA[11]*inv, accA[15]*inv);
    }
    if (two) {
        float m = accB[0];
#pragma unroll
        for (int t = 1; t < NT; t++) m = fmaxf(m, accB[t]);
        float s = 0.0f;
#pragma unroll
        for (int t = 0; t < NT; t++) { accB[t] = __expf(accB[t] - m); s += accB[t]; }
        float inv = 1.0f / s;
        float4* o = (float4*)(g_p + (size_t)(node0 + 1) * NT);
        o[0] = make_float4(accB[0]*inv, accB[4]*inv, accB[8]*inv,  accB[12]*inv);
        o[1] = make_float4(accB[1]*inv, accB[5]*inv, accB[9]*inv,  accB[13]*inv);
        o[2] = make_float4(accB[2]*inv, accB[6]*inv, accB[10]*inv, accB[14]*inv);
        o[3] = make_float4(accB[3]*inv, accB[7]*inv, accB[11]*inv, accB[15]*inv);
    }
}

// ---------------------------------------------------------------------------
// Scatter: msum[dst] += p[src].  4 lanes per edge, 2 edges per thread
// (validated R10/R13). RED #j across an edge's 4 lanes covers 16 contiguous
// bytes. No degree atomics (row-sum trick).
// ---------------------------------------------------------------------------
__global__ void k_scatter(const void* __restrict__ srcv,
                          const void* __restrict__ dstv,
                          int E, int n) {
    int gid = blockIdx.x * blockDim.x + threadIdx.x;
    int pair = gid >> 2;
    int e0 = pair * 2;
    if (e0 >= E) return;
    int q = gid & 3;
    bool has2 = (e0 + 1 < E);

    int s0, d0, s1 = 0, d1 = 0;
    if (g_idx64) {
        const longlong2* ps = (const longlong2*)srcv;
        const longlong2* pd = (const longlong2*)dstv;
        longlong2 sv = ps[pair];
        longlong2 dv = pd[pair];
        s0 = (int)sv.x; s1 = (int)sv.y;
        d0 = (int)dv.x; d1 = (int)dv.y;
    } else {
        const int2* ps = (const int2*)srcv;
        const int2* pd = (const int2*)dstv;
        int2 sv = ps[pair];
        int2 dv = pd[pair];
        s0 = sv.x; s1 = sv.y;
        d0 = dv.x; d1 = dv.y;
    }
    s0 = min(max(s0, 0), n - 1);
    d0 = min(max(d0, 0), n - 1);

    const float4 v0 = __ldg((const float4*)(g_p + (size_t)s0 * NT + q * 4));
    float* row0 = g_msum + (size_t)d0 * NT + q;
    atomicAdd(row0 + 0,  v0.x);
    atomicAdd(row0 + 4,  v0.y);
    atomicAdd(row0 + 8,  v0.z);
    atomicAdd(row0 + 12, v0.w);

    if (has2) {
        s1 = min(max(s1, 0), n - 1);
        d1 = min(max(d1, 0), n - 1);
        const float4 v1 = __ldg((const float4*)(g_p + (size_t)s1 * NT + q * 4));
        float* row1 = g_msum + (size_t)d1 * NT + q;
        atomicAdd(row1 + 0,  v1.x);
        atomicAdd(row1 + 4,  v1.y);
        atomicAdd(row1 + 8,  v1.z);
        atomicAdd(row1 + 12, v1.w);
    }
}

// ---------------------------------------------------------------------------
// out = relu(invd * (msum @ Wf) + bf)  with invd = 1/max(round(rowsum),1).
// v3: smem staging. Block stages TILE_N=64 msum rows (4KB) coalesced, each
// 4-lane group butterfly-reduces its row sum -> sinv[]. Compute loop reads
// rows via broadcast LDS (29cyc, no global latency) and writes coalesced.
// Normalization folded in by linearity -> k_norm kernel eliminated.
// ---------------------------------------------------------------------------
__global__ void __launch_bounds__(256) k_final(
        const float* __restrict__ Wf,
        const float* __restrict__ bf,
        float* __restrict__ out,
        int n) {
    __shared__ __align__(16) float srow[TILE_N * NT];   // 4KB
    __shared__ float sinv[TILE_N];

    int tid = threadIdx.x;
    int j   = tid & 127;
    int sub = tid >> 7;          // 0 or 1

    // weights packed as 8 u64 t-pairs (registers, loop-invariant)
    u64 w2[8];
#pragma unroll
    for (int i = 0; i < 8; i++) {
        PACK2(w2[i], Wf[(2 * i) * OD + j], Wf[(2 * i + 1) * OD + j]);
    }
    float bj = bf[j];

    int ntiles = (n + TILE_N - 1) / TILE_N;
    for (int tile = blockIdx.x; tile < ntiles; tile += gridDim.x) {
        int base   = tile * TILE_N;
        int nnodes = min(TILE_N, n - base);

        // stage: thread i loads float4 #(i&3) of node base+(i>>2)  (coalesced)
        if (tid < nnodes * 4) {
            float4 v = ((const float4*)(g_msum + (size_t)base * NT))[tid];
            ((float4*)srow)[tid] = v;
            // row sum via 4-lane butterfly (p rows sum to 1 -> sum == degree)
            float s = (v.x + v.y) + (v.z + v.w);
            s += __shfl_xor_sync(0xffffffffu, s, 1);
            s += __shfl_xor_sync(0xffffffffu, s, 2);
            if ((tid & 3) == 0)
                sinv[tid >> 2] = 1.0f / fmaxf(nearbyintf(s), 1.0f);
        }
        __syncthreads();

        // compute: thread handles nodes sub, sub+2, ... at column j
        for (int nn = sub; nn < nnodes; nn += 2) {
            const longlong2* rw = (const longlong2*)(srow + nn * NT);
            longlong2 a0 = rw[0], a1 = rw[1], a2 = rw[2], a3 = rw[3];

            u64 acc = 0ULL;
            FMA2(acc, (u64)a0.x, w2[0], acc);
            FMA2(acc, (u64)a0.y, w2[1], acc);
            FMA2(acc, (u64)a1.x, w2[2], acc);
            FMA2(acc, (u64)a1.y, w2[3], acc);
            FMA2(acc, (u64)a2.x, w2[4], acc);
            FMA2(acc, (u64)a2.y, w2[5], acc);
            FMA2(acc, (u64)a3.x, w2[6], acc);
            FMA2(acc, (u64)a3.y, w2[7], acc);
            float al, ah;
            UNPACK2(al, ah, acc);
            float v = fmaf(sinv[nn], al + ah, bj);
            out[(size_t)(base + nn) * OD + j] = fmaxf(v, 0.0f);
        }
        __syncthreads();   // protect srow before next tile's staging
    }
}

// ---------------------------------------------------------------------------
// Inputs (metadata order): r, src, dst, W1, b1, Wp, bp, Wf, bf
// ---------------------------------------------------------------------------
extern "C" void kernel_launch(void* const* d_in, const int* in_sizes, int n_in,
                              void* d_out, int out_size) {
    const float* r   = (const float*)d_in[0];
    const void*  src = d_in[1];
    const void*  dst = d_in[2];
    const float* W1  = (const float*)d_in[3];
    const float* b1  = (const float*)d_in[4];
    const float* Wp  = (const float*)d_in[5];
    const float* bp  = (const float*)d_in[6];
    const float* Wf  = (const float*)d_in[7];
    const float* bf  = (const float*)d_in[8];
    float*       out = (float*)d_out;

    int n = in_sizes[0] / NT;
    int E = in_sizes[1];
    if (n > N_MAX) n = N_MAX;

    k_compute_p<<<((n + 1) / 2 + 127) / 128, 128>>>(r, W1, b1, Wp, bp, src, E, n);
    {
        long long threads = (long long)((E + 1) / 2) * 4;
        int blocks = (int)((threads + 255) / 256);
        k_scatter<<<blocks, 256>>>(src, dst, E, n);
    }
    {
        int ntiles = (n + TILE_N - 1) / TILE_N;
        int blocks = min(ntiles, 1184);   // 8 blocks/SM x 148 SMs
        k_final<<<blocks, 256>>>(Wf, bf, out, n);
    }
}